// round 2
// baseline (speedup 1.0000x reference)
#include <cuda_runtime.h>
#include <cstddef>

#define FULLMASK 0xffffffffu

// Profile-HMM forward algorithm in scaled linear space.
// One warp per batch element. Lane j owns states k = 2j and 2j+1 (k in 0..63).
// State k = 64 is a sink tracked as warp-replicated scalars.
// The delete-chain fD[k] = aM2D[k-1]*fM[k-1] + aD2D[k-1]*fD[k-1] is a first-order
// affine recurrence, evaluated with a Kogge-Stone warp scan whose multiplicative
// composites (products of aD2D) are precomputed outside the L-loop.
__global__ void __launch_bounds__(256)
phmm_vae_kernel(const int* __restrict__ x,
                const float* __restrict__ a,
                const float* __restrict__ e,
                const float* __restrict__ mus,
                const float* __restrict__ logvars,
                float* __restrict__ out,
                int B, int Edim, float inv_B)
{
    constexpr int K = 64;
    constexpr int L = 128;

    int gtid = blockIdx.x * blockDim.x + threadIdx.x;
    int warp = gtid >> 5;
    int lane = gtid & 31;
    if (warp >= B) return;

    const float* ab = a + (size_t)warp * (K + 1) * 7;
    const float* eb = e + (size_t)warp * K * 4;
    const int*   xb = x + (size_t)warp * L;

    const int k0 = lane * 2;
    const int k1 = lane * 2 + 1;

    // ---- Convert transitions to linear space (enum: M2M,M2I,M2D,I2M,I2I,D2M,D2D) ----
    const float* A0 = ab + k0 * 7;
    const float* A1 = ab + k1 * 7;
    float M2M0  = __expf(A0[0]);
    float qM2I0 = 0.25f * __expf(A0[1]);   // fold LOG_Q = log(0.25)
    float M2D0  = __expf(A0[2]);
    float I2M0  = __expf(A0[3]);
    float qI2I0 = 0.25f * __expf(A0[4]);
    float D2M0  = __expf(A0[5]);
    float c0    = __expf(A0[6]);           // aD2D at k0

    float M2M1  = __expf(A1[0]);
    float qM2I1 = 0.25f * __expf(A1[1]);
    float M2D1  = __expf(A1[2]);
    float I2M1  = __expf(A1[3]);
    float qI2I1 = 0.25f * __expf(A1[4]);
    float D2M1  = __expf(A1[5]);
    float c1    = __expf(A1[6]);           // aD2D at k1

    // k = 64 sink transitions (broadcast loads)
    const float* A64 = ab + K * 7;
    float M2M64  = __expf(A64[0]);
    float qM2I64 = 0.25f * __expf(A64[1]);
    float I2M64  = __expf(A64[3]);
    float qI2I64 = 0.25f * __expf(A64[4]);
    float D2M64  = __expf(A64[5]);

    // ---- Emissions (linear) ----
    float4 ev0 = reinterpret_cast<const float4*>(eb)[k0];
    float4 ev1 = reinterpret_cast<const float4*>(eb)[k1];
    float e00 = __expf(ev0.x), e01 = __expf(ev0.y), e02 = __expf(ev0.z), e03 = __expf(ev0.w);
    float e10 = __expf(ev1.x), e11 = __expf(ev1.y), e12 = __expf(ev1.z), e13 = __expf(ev1.w);

    // ---- Precompute Kogge-Stone self-composites for the delete-chain scan ----
    // Per-lane affine segment: C_lane = c0*c1 (fixed across all L iterations).
    float Cself[5];
    {
        float Crun = c0 * c1;
        #pragma unroll
        for (int s = 0; s < 5; s++) {
            Cself[s] = Crun;
            float Cin = __shfl_up_sync(FULLMASK, Crun, 1 << s);
            if (lane >= (1 << s)) Crun *= Cin;
        }
    }

    // ---- State init (linear space): fM[0]=1 else 0; fI=0; sink states 0 ----
    float fM0 = (lane == 0) ? 1.0f : 0.0f;
    float fM1 = 0.0f;
    float fI0 = 0.0f, fI1 = 0.0f;
    float fM64 = 0.0f, fI64 = 0.0f;
    int   S = 0;               // stored = true * 2^S
    float fD64 = 0.0f;

    #pragma unroll 1
    for (int l = 0; l <= L; l++) {
        // ---- delete-chain scan over current fM:
        //      g[i] = aM2D[i]*fM[i] + aD2D[i]*g[i-1], i = 0..63, g[-1] = 0 ----
        float d0 = M2D0 * fM0;
        float d1 = M2D1 * fM1;
        float D  = fmaf(c1, d0, d1);          // lane-local inclusive composite D
        #pragma unroll
        for (int s = 0; s < 5; s++) {
            float Din = __shfl_up_sync(FULLMASK, D, 1 << s);
            if (lane >= (1 << s)) D = fmaf(Cself[s], Din, D);
        }
        float gexcl = __shfl_up_sync(FULLMASK, D, 1);   // g[2j-1]
        if (lane == 0) gexcl = 0.0f;

        if (l == L) {                          // final: need fD[64] = g[63]
            fD64 = __shfl_sync(FULLMASK, D, 31);
            break;
        }

        float fDa = gexcl;                     // fD[2j]   (fD[0] = 0)
        float fDb = fmaf(c0, gexcl, d0);       // fD[2j+1] = g[2j]

        // ---- emission select ----
        int xv = xb[l];
        float es0 = (xv == 0) ? e00 : ((xv == 1) ? e01 : ((xv == 2) ? e02 : e03));
        float es1 = (xv == 0) ? e10 : ((xv == 1) ? e11 : ((xv == 2) ? e12 : e13));

        // ---- prev / new match states ----
        float prev0 = fmaf(M2M0, fM0, fmaf(I2M0, fI0, D2M0 * fDa));
        float prev1 = fmaf(M2M1, fM1, fmaf(I2M1, fI1, D2M1 * fDb));
        float p0 = es0 * prev0;
        float p1 = es1 * prev1;

        float p1up = __shfl_up_sync(FULLMASK, p1, 1);   // p[2j-1]
        float p63  = __shfl_sync(FULLMASK, p1, 31);     // p[63] -> fM[64]

        // ---- insert states (use OLD fM/fI) ----
        float nfI0 = fmaf(qM2I0, fM0, qI2I0 * fI0);
        float nfI1 = fmaf(qM2I1, fM1, qI2I1 * fI1);
        fI64 = fmaf(qM2I64, fM64, qI2I64 * fI64);
        fM64 = p63;

        fM0 = (lane == 0) ? 0.0f : p1up;
        fM1 = p0;
        fI0 = nfI0;
        fI1 = nfI1;

        // ---- warp-uniform power-of-two rescale (keep max near 2^32) ----
        float m = fmaxf(fmaxf(fmaxf(fM0, fM1), fmaxf(fI0, fI1)), fmaxf(fM64, fI64));
        unsigned mb = __reduce_max_sync(FULLMASK, __float_as_uint(m));
        int Eexp = (int)(mb >> 23) - 127;
        int se = 32 - Eexp;
        se = max(-126, min(126, se));
        float scale = __int_as_float((unsigned)(127 + se) << 23);
        S += se;
        fM0 *= scale; fM1 *= scale;
        fI0 *= scale; fI1 *= scale;
        fM64 *= scale; fI64 *= scale;
    }

    // ---- final logsumexp (linear) + unscale ----
    float fin  = fmaf(M2M64, fM64, fmaf(I2M64, fI64, D2M64 * fD64));
    float loss = (float)S * 0.69314718055994531f - logf(fin);

    // ---- KLD for this batch element ----
    float kl = 0.0f;
    for (int i = lane; i < Edim; i += 32) {
        float mu = mus[(size_t)warp * Edim + i];
        float lv = logvars[(size_t)warp * Edim + i];
        kl += fmaf(mu, mu, __expf(lv)) - 1.0f - lv;
    }
    kl *= 0.5f;
    #pragma unroll
    for (int off = 16; off >= 1; off >>= 1)
        kl += __shfl_xor_sync(FULLMASK, kl, off);

    if (lane == 0)
        atomicAdd(out, (loss + kl) * inv_B);
}

extern "C" void kernel_launch(void* const* d_in, const int* in_sizes, int n_in,
                              void* d_out, int out_size)
{
    const int*   x   = (const int*)  d_in[0];   // batch_input (B, L) int32
    const float* a   = (const float*)d_in[1];   // transition_probs (B, K+1, 7)
    const float* e   = (const float*)d_in[2];   // emission_probs (B, K, 4)
    const float* mus = (const float*)d_in[3];   // (B, E)
    const float* lv  = (const float*)d_in[4];   // (B, E)

    const int L = 128;
    int B = in_sizes[0] / L;
    int Edim = (B > 0) ? (in_sizes[3] / B) : 16;

    cudaMemsetAsync(d_out, 0, sizeof(float), 0);

    int threads = 256;                 // 8 warps/block, 1 warp per batch element
    int total_threads = B * 32;
    int blocks = (total_threads + threads - 1) / threads;
    phmm_vae_kernel<<<blocks, threads>>>(x, a, e, mus, lv, (float*)d_out,
                                         B, Edim, 1.0f / (float)B);
}

// round 3
// speedup vs baseline: 1.2191x; 1.2191x over previous
#include <cuda_runtime.h>
#include <cstddef>

#define FULLMASK 0xffffffffu

typedef unsigned long long u64;

// ---- f32x2 packed helpers (sm_103a) ----
__device__ __forceinline__ u64 pk2(float lo, float hi) {
    u64 r; asm("mov.b64 %0, {%1, %2};" : "=l"(r) : "f"(lo), "f"(hi)); return r;
}
__device__ __forceinline__ void upk2(u64 v, float& lo, float& hi) {
    asm("mov.b64 {%0, %1}, %2;" : "=f"(lo), "=f"(hi) : "l"(v));
}
__device__ __forceinline__ u64 fma2(u64 a, u64 b, u64 c) {
    u64 d; asm("fma.rn.f32x2 %0, %1, %2, %3;" : "=l"(d) : "l"(a), "l"(b), "l"(c)); return d;
}
__device__ __forceinline__ u64 mul2(u64 a, u64 b) {
    u64 d; asm("mul.rn.f32x2 %0, %1, %2;" : "=l"(d) : "l"(a), "l"(b)); return d;
}
// 4-way packed select by symbol (3 SETP + 3 SELP.b64)
__device__ __forceinline__ u64 esel4(u64 E0, u64 E1, u64 E2, u64 E3, int xv) {
    u64 r;
    asm("{\n\t"
        ".reg .pred p0, p1, p2;\n\t"
        "setp.eq.s32 p0, %5, 0;\n\t"
        "setp.eq.s32 p1, %5, 1;\n\t"
        "setp.eq.s32 p2, %5, 2;\n\t"
        "selp.b64 %0, %3, %4, p2;\n\t"
        "selp.b64 %0, %2, %0, p1;\n\t"
        "selp.b64 %0, %1, %0, p0;\n\t"
        "}"
        : "=l"(r) : "l"(E0), "l"(E1), "l"(E2), "l"(E3), "r"(xv));
    return r;
}

// Profile-HMM forward algorithm in scaled linear space.
// One warp per batch element. Lane j owns states k = 2j, 2j+1 packed as f32x2.
// Delete-chain handled by a Kogge-Stone warp scan over per-lane scalar composites.
__global__ void __launch_bounds__(256)
phmm_vae_kernel(const int* __restrict__ x,
                const float* __restrict__ a,
                const float* __restrict__ e,
                const float* __restrict__ mus,
                const float* __restrict__ logvars,
                float* __restrict__ out,
                int B, int Edim, float inv_B)
{
    constexpr int K = 64;
    constexpr int L = 128;

    int gtid = blockIdx.x * blockDim.x + threadIdx.x;
    int warp = gtid >> 5;
    int lane = gtid & 31;
    if (warp >= B) return;

    const float* ab = a + (size_t)warp * (K + 1) * 7;
    const float* eb = e + (size_t)warp * K * 4;
    const int*   xb = x + (size_t)warp * L;

    const int k0 = lane * 2;
    const int k1 = lane * 2 + 1;

    // ---- transitions -> linear space (enum: M2M,M2I,M2D,I2M,I2I,D2M,D2D) ----
    const float* A0 = ab + k0 * 7;
    const float* A1 = ab + k1 * 7;
    float M2D0 = __expf(A0[2]);
    float M2D1 = __expf(A1[2]);
    float c0   = __expf(A0[6]);
    float c1   = __expf(A1[6]);

    u64 M2Mp  = pk2(__expf(A0[0]), __expf(A1[0]));
    u64 qM2Ip = pk2(0.25f * __expf(A0[1]), 0.25f * __expf(A1[1]));
    u64 I2Mp  = pk2(__expf(A0[3]), __expf(A1[3]));
    u64 qI2Ip = pk2(0.25f * __expf(A0[4]), 0.25f * __expf(A1[4]));
    u64 D2Mp  = pk2(__expf(A0[5]), __expf(A1[5]));

    // k = 64 sink transitions
    const float* A64 = ab + K * 7;
    float M2M64  = __expf(A64[0]);
    float qM2I64 = 0.25f * __expf(A64[1]);
    float I2M64  = __expf(A64[3]);
    float qI2I64 = 0.25f * __expf(A64[4]);
    float D2M64  = __expf(A64[5]);

    // ---- emissions (linear), packed (state0, state1) per symbol ----
    float4 ev0 = reinterpret_cast<const float4*>(eb)[k0];
    float4 ev1 = reinterpret_cast<const float4*>(eb)[k1];
    u64 E0p = pk2(__expf(ev0.x), __expf(ev1.x));
    u64 E1p = pk2(__expf(ev0.y), __expf(ev1.y));
    u64 E2p = pk2(__expf(ev0.z), __expf(ev1.z));
    u64 E3p = pk2(__expf(ev0.w), __expf(ev1.w));

    // ---- masked Kogge-Stone composites (fixed across L) ----
    float Cm[5];
    {
        float Crun = c0 * c1;
        #pragma unroll
        for (int s = 0; s < 5; s++) {
            Cm[s] = (lane >= (1 << s)) ? Crun : 0.0f;
            float Cin = __shfl_up_sync(FULLMASK, Crun, 1 << s);
            if (lane >= (1 << s)) Crun *= Cin;
        }
    }

    // ---- state init (linear): fM[0]=1 else 0; fI=0; sinks 0 ----
    float fM0s = (lane == 0) ? 1.0f : 0.0f;
    float fM1s = 0.0f;
    u64   fIp  = 0ull;          // packed (fI_2j, fI_2j+1) = (0,0)
    float fM64 = 0.0f, fI64 = 0.0f;
    int   S = 0;                // stored = true * 2^S

    const int4* x4 = reinterpret_cast<const int4*>(xb);

    #pragma unroll 1
    for (int g = 0; g < L / 4; g++) {
        int4 xq = x4[g];

        #pragma unroll
        for (int sub = 0; sub < 4; sub++) {
            int xv = (sub == 0) ? xq.x : (sub == 1) ? xq.y : (sub == 2) ? xq.z : xq.w;

            // ---- delete-chain scan over current fM ----
            float d0 = M2D0 * fM0s;
            float d1 = M2D1 * fM1s;
            float D  = fmaf(c1, d0, d1);
            #pragma unroll
            for (int s = 0; s < 5; s++) {
                float Din = __shfl_up_sync(FULLMASK, D, 1 << s);
                D = fmaf(Cm[s], Din, D);
            }
            float gexcl = __shfl_up_sync(FULLMASK, D, 1);
            float fDa = (lane == 0) ? 0.0f : gexcl;    // fD[2j]
            float fDb = fmaf(c0, fDa, d0);             // fD[2j+1]
            u64 fDp = pk2(fDa, fDb);

            // ---- emissions + match update (packed) ----
            u64 esp   = esel4(E0p, E1p, E2p, E3p, xv);
            u64 fMp   = pk2(fM0s, fM1s);
            u64 prevp = fma2(M2Mp, fMp, fma2(I2Mp, fIp, mul2(D2Mp, fDp)));
            u64 pp    = mul2(esp, prevp);
            float p0, p1; upk2(pp, p0, p1);

            float p1up = __shfl_up_sync(FULLMASK, p1, 1);
            float p63  = __shfl_sync(FULLMASK, p1, 31);

            // ---- insert states (use OLD fM/fI) ----
            fIp  = fma2(qM2Ip, fMp, mul2(qI2Ip, fIp));
            fI64 = fmaf(qM2I64, fM64, qI2I64 * fI64);
            fM64 = p63;

            fM0s = (lane == 0) ? 0.0f : p1up;
            fM1s = p0;

            // ---- rescale every 2nd step (power-of-two, warp-uniform) ----
            if (sub & 1) {
                float fi0, fi1; upk2(fIp, fi0, fi1);
                float m = fmaxf(fmaxf(fmaxf(fM0s, fM1s), fmaxf(fi0, fi1)),
                                fmaxf(fM64, fI64));
                unsigned mb = __reduce_max_sync(FULLMASK, __float_as_uint(m));
                int Eexp = (int)(mb >> 23) - 127;
                int se = 32 - Eexp;
                se = max(-126, min(126, se));
                float scale = __int_as_float((unsigned)(127 + se) << 23);
                S += se;
                u64 scp = pk2(scale, scale);
                fM0s *= scale; fM1s *= scale;
                fIp = mul2(fIp, scp);
                fM64 *= scale; fI64 *= scale;
            }
        }
    }

    // ---- final delete-chain for fD[64] ----
    float fD64;
    {
        float d0 = M2D0 * fM0s;
        float d1 = M2D1 * fM1s;
        float D  = fmaf(c1, d0, d1);
        #pragma unroll
        for (int s = 0; s < 5; s++) {
            float Din = __shfl_up_sync(FULLMASK, D, 1 << s);
            D = fmaf(Cm[s], Din, D);
        }
        fD64 = __shfl_sync(FULLMASK, D, 31);
    }

    // ---- final logsumexp (linear) + unscale ----
    float fin  = fmaf(M2M64, fM64, fmaf(I2M64, fI64, D2M64 * fD64));
    float loss = (float)S * 0.69314718055994531f - logf(fin);

    // ---- KLD for this batch element ----
    float kl = 0.0f;
    for (int i = lane; i < Edim; i += 32) {
        float mu = mus[(size_t)warp * Edim + i];
        float lv = logvars[(size_t)warp * Edim + i];
        kl += fmaf(mu, mu, __expf(lv)) - 1.0f - lv;
    }
    kl *= 0.5f;
    #pragma unroll
    for (int off = 16; off >= 1; off >>= 1)
        kl += __shfl_xor_sync(FULLMASK, kl, off);

    if (lane == 0)
        atomicAdd(out, (loss + kl) * inv_B);
}

extern "C" void kernel_launch(void* const* d_in, const int* in_sizes, int n_in,
                              void* d_out, int out_size)
{
    const int*   x   = (const int*)  d_in[0];   // batch_input (B, L) int32
    const float* a   = (const float*)d_in[1];   // transition_probs (B, K+1, 7)
    const float* e   = (const float*)d_in[2];   // emission_probs (B, K, 4)
    const float* mus = (const float*)d_in[3];   // (B, E)
    const float* lv  = (const float*)d_in[4];   // (B, E)

    const int L = 128;
    int B = in_sizes[0] / L;
    int Edim = (B > 0) ? (in_sizes[3] / B) : 16;

    cudaMemsetAsync(d_out, 0, sizeof(float), 0);

    int threads = 256;                 // 8 warps/block, 1 warp per batch element
    int total_threads = B * 32;
    int blocks = (total_threads + threads - 1) / threads;
    phmm_vae_kernel<<<blocks, threads>>>(x, a, e, mus, lv, (float*)d_out,
                                         B, Edim, 1.0f / (float)B);
}

// round 6
// speedup vs baseline: 1.3640x; 1.1189x over previous
#include <cuda_runtime.h>
#include <cstddef>

#define FULLMASK 0xffffffffu
typedef unsigned long long u64;

// ---- f32x2 packed helpers (sm_103a) ----
__device__ __forceinline__ u64 pk2(float lo, float hi) {
    u64 r; asm("mov.b64 %0, {%1, %2};" : "=l"(r) : "f"(lo), "f"(hi)); return r;
}
__device__ __forceinline__ void upk2(u64 v, float& lo, float& hi) {
    asm("mov.b64 {%0, %1}, %2;" : "=f"(lo), "=f"(hi) : "l"(v));
}
__device__ __forceinline__ u64 fma2(u64 a, u64 b, u64 c) {
    u64 d; asm("fma.rn.f32x2 %0, %1, %2, %3;" : "=l"(d) : "l"(a), "l"(b), "l"(c)); return d;
}
__device__ __forceinline__ u64 mul2(u64 a, u64 b) {
    u64 d; asm("mul.rn.f32x2 %0, %1, %2;" : "=l"(d) : "l"(a), "l"(b)); return d;
}

// Profile-HMM forward in scaled linear space.
// HALF-WARP per batch element: lanes 0-15 = batch 2w, lanes 16-31 = batch 2w+1.
// Each lane owns 4 states k = 4*hl .. 4*hl+3 (two f32x2 pairs).
// Delete-chain: per-lane local affine combine, then depth-4 Kogge-Stone scan
// over 16 lanes (masked composites; shuffles serve both halves at once).
__global__ void __launch_bounds__(256, 2)
phmm_vae_kernel(const int* __restrict__ x,
                const float* __restrict__ a,
                const float* __restrict__ e,
                const float* __restrict__ mus,
                const float* __restrict__ logvars,
                float* __restrict__ out,
                int B, int Edim, float inv_B)
{
    constexpr int K = 64;
    constexpr int L = 128;

    __shared__ float4 sem[8][2][4][16];   // [warp][half][sym][hl] : 16 KB

    int tid  = threadIdx.x;
    int wp   = tid >> 5;
    int lane = tid & 31;
    int hl   = lane & 15;
    int half = lane >> 4;
    int gwarp = blockIdx.x * 8 + wp;
    if (gwarp * 2 >= B) return;           // whole warp out of range
    int bb  = gwarp * 2 + half;           // this half's batch element
    int bbc = min(bb, B - 1);

    const float* ab = a + (size_t)bbc * (K + 1) * 7;
    const float* eb = e + (size_t)bbc * K * 4;
    const int*   xb = x + (size_t)bbc * L;

    const int k0 = hl * 4;
    const float* A = ab + k0 * 7;

    // ---- transitions -> linear (enum: M2M,M2I,M2D,I2M,I2I,D2M,D2D) ----
    float c0 = __expf(A[6]),  c1 = __expf(A[13]),
          c2 = __expf(A[20]), c3 = __expf(A[27]);
    u64 M2DA = pk2(__expf(A[2]),  __expf(A[9]));
    u64 M2DB = pk2(__expf(A[16]), __expf(A[23]));
    u64 M2MA = pk2(__expf(A[0]),  __expf(A[7]));
    u64 M2MB = pk2(__expf(A[14]), __expf(A[21]));
    u64 qM2IA = pk2(0.25f*__expf(A[1]),  0.25f*__expf(A[8]));
    u64 qM2IB = pk2(0.25f*__expf(A[15]), 0.25f*__expf(A[22]));
    u64 I2MA = pk2(__expf(A[3]),  __expf(A[10]));
    u64 I2MB = pk2(__expf(A[17]), __expf(A[24]));
    u64 qI2IA = pk2(0.25f*__expf(A[4]),  0.25f*__expf(A[11]));
    u64 qI2IB = pk2(0.25f*__expf(A[18]), 0.25f*__expf(A[25]));
    u64 D2MA = pk2(__expf(A[5]),  __expf(A[12]));
    u64 D2MB = pk2(__expf(A[19]), __expf(A[26]));

    // local delete-chain combine coefficients:
    // D_local = d3 + c3*d2 + c3c2*d1 + c3c2c1*d0
    u64 KA = pk2(c3 * c2 * c1, c3 * c2);
    u64 KB = pk2(c3, 1.0f);

    // sink k = 64
    const float* A64 = ab + K * 7;
    float M2M64  = __expf(A64[0]);
    float qM2I64 = 0.25f * __expf(A64[1]);
    float I2M64  = __expf(A64[3]);
    float qI2I64 = 0.25f * __expf(A64[4]);
    float D2M64  = __expf(A64[5]);

    // ---- emissions -> linear -> smem, laid out by symbol ----
    {
        const float4* e4 = reinterpret_cast<const float4*>(eb) + k0;
        float4 r0 = e4[0], r1 = e4[1], r2 = e4[2], r3 = e4[3];
        sem[wp][half][0][hl] = make_float4(__expf(r0.x), __expf(r1.x), __expf(r2.x), __expf(r3.x));
        sem[wp][half][1][hl] = make_float4(__expf(r0.y), __expf(r1.y), __expf(r2.y), __expf(r3.y));
        sem[wp][half][2][hl] = make_float4(__expf(r0.z), __expf(r1.z), __expf(r2.z), __expf(r3.z));
        sem[wp][half][3][hl] = make_float4(__expf(r0.w), __expf(r1.w), __expf(r2.w), __expf(r3.w));
    }
    __syncwarp();
    const float4* semb = &sem[wp][half][0][hl];   // + sym*16 per symbol

    // ---- masked Kogge-Stone composites over 16 lanes (fixed across L) ----
    float Cm[4];
    {
        float Crun = c0 * c1 * c2 * c3;
        #pragma unroll
        for (int s = 0; s < 4; s++) {
            Cm[s] = (hl >= (1 << s)) ? Crun : 0.0f;
            float Cin = __shfl_up_sync(FULLMASK, Crun, 1 << s);
            if (hl >= (1 << s)) Crun *= Cin;
        }
    }

    // ---- state init (linear): fM[0]=1 else 0; fI=0; sinks 0 ----
    u64 fMA = (hl == 0) ? pk2(1.0f, 0.0f) : 0ull;   // states (4hl, 4hl+1)
    u64 fMB = 0ull;                                  // states (4hl+2, 4hl+3)
    u64 fIA = 0ull, fIB = 0ull;
    float fM64 = 0.0f, fI64 = 0.0f;
    int S = 0;
    const int bidx = (lane & 16) | 15;               // hl==15 lane of own half
    const unsigned hmask = half ? 0xFFFF0000u : 0x0000FFFFu;

    const int4* x4 = reinterpret_cast<const int4*>(xb);

    #pragma unroll 1
    for (int g = 0; g < L / 4; g++) {
        int4 xq = x4[g];

        #pragma unroll
        for (int sub = 0; sub < 4; sub++) {
            int xv = (sub == 0) ? xq.x : (sub == 1) ? xq.y : (sub == 2) ? xq.z : xq.w;

            // ---- delete-chain: d[i] = M2D[i]*fM[i]; local inclusive combine ----
            u64 dA = mul2(M2DA, fMA);
            u64 dB = mul2(M2DB, fMB);
            u64 t  = fma2(KA, dA, mul2(KB, dB));
            float tlo, thi; upk2(t, tlo, thi);
            float D = tlo + thi;
            #pragma unroll
            for (int s = 0; s < 4; s++) {
                float Din = __shfl_up_sync(FULLMASK, D, 1 << s);
                D = fmaf(Cm[s], Din, D);
            }
            float gx = __shfl_up_sync(FULLMASK, D, 1);
            gx = (hl == 0) ? 0.0f : gx;              // g[4hl-1]

            float d0, d1, d2, d3;
            upk2(dA, d0, d1); upk2(dB, d2, d3);
            float fD1 = fmaf(c0, gx, d0);
            float fD2 = fmaf(c1, fD1, d1);
            float fD3 = fmaf(c2, fD2, d2);
            u64 fDA = pk2(gx, fD1);
            u64 fDB = pk2(fD2, fD3);

            // ---- emission (1 LDS.128) ----
            float4 es = semb[xv * 16];
            u64 esA = pk2(es.x, es.y);
            u64 esB = pk2(es.z, es.w);

            // ---- match ----
            u64 prevA = fma2(M2MA, fMA, fma2(I2MA, fIA, mul2(D2MA, fDA)));
            u64 prevB = fma2(M2MB, fMB, fma2(I2MB, fIB, mul2(D2MB, fDB)));
            u64 pA = mul2(esA, prevA);
            u64 pB = mul2(esB, prevB);
            float p0, p1, p2, p3;
            upk2(pA, p0, p1); upk2(pB, p2, p3);

            float p3up = __shfl_up_sync(FULLMASK, p3, 1);
            p3up = (hl == 0) ? 0.0f : p3up;
            float plast = __shfl_sync(FULLMASK, p3, bidx);

            // ---- insert (OLD fM/fI) ----
            fIA = fma2(qM2IA, fMA, mul2(qI2IA, fIA));
            fIB = fma2(qM2IB, fMB, mul2(qI2IB, fIB));
            fI64 = fmaf(qM2I64, fM64, qI2I64 * fI64);
            fM64 = plast;

            fMA = pk2(p3up, p0);
            fMB = pk2(p1, p2);

            // ---- rescale every 2nd step (per-half, power-of-two, target 2^0) ----
            if (sub & 1) {
                float a0, a1, b0, b1, i0, i1, j0, j1;
                upk2(fMA, a0, a1); upk2(fMB, b0, b1);
                upk2(fIA, i0, i1); upk2(fIB, j0, j1);
                float m = fmaxf(fmaxf(fmaxf(a0, a1), fmaxf(b0, b1)),
                                fmaxf(fmaxf(i0, i1), fmaxf(j0, j1)));
                m = fmaxf(m, fmaxf(fM64, fI64));
                unsigned mb = __reduce_max_sync(hmask, __float_as_uint(m));
                int se = 127 - (int)(mb >> 23);
                se = max(-126, min(126, se));
                float scale = __int_as_float((unsigned)(127 + se) << 23);
                S += se;
                u64 scp = pk2(scale, scale);
                fMA = mul2(fMA, scp); fMB = mul2(fMB, scp);
                fIA = mul2(fIA, scp); fIB = mul2(fIB, scp);
                fM64 *= scale; fI64 *= scale;
            }
        }
    }

    // ---- final delete-chain for fD[64] ----
    float fD64;
    {
        u64 dA = mul2(M2DA, fMA);
        u64 dB = mul2(M2DB, fMB);
        u64 t  = fma2(KA, dA, mul2(KB, dB));
        float tlo, thi; upk2(t, tlo, thi);
        float D = tlo + thi;
        #pragma unroll
        for (int s = 0; s < 4; s++) {
            float Din = __shfl_up_sync(FULLMASK, D, 1 << s);
            D = fmaf(Cm[s], Din, D);
        }
        fD64 = __shfl_sync(FULLMASK, D, bidx);
    }

    // ---- final logsumexp (linear) + unscale ----
    float fin  = fmaf(M2M64, fM64, fmaf(I2M64, fI64, D2M64 * fD64));
    float loss = (float)S * 0.69314718055994531f - logf(fin);

    // ---- KLD (16 lanes per batch element) ----
    float kl = 0.0f;
    for (int i = hl; i < Edim; i += 16) {
        float mu = mus[(size_t)bbc * Edim + i];
        float lv = logvars[(size_t)bbc * Edim + i];
        kl += fmaf(mu, mu, __expf(lv)) - 1.0f - lv;
    }
    kl *= 0.5f;
    #pragma unroll
    for (int off = 8; off >= 1; off >>= 1)
        kl += __shfl_xor_sync(FULLMASK, kl, off);   // stays within half (off < 16)

    if (hl == 0 && bb < B)
        atomicAdd(out, (loss + kl) * inv_B);
}

extern "C" void kernel_launch(void* const* d_in, const int* in_sizes, int n_in,
                              void* d_out, int out_size)
{
    const int*   x   = (const int*)  d_in[0];   // batch_input (B, L) int32
    const float* a   = (const float*)d_in[1];   // transition_probs (B, K+1, 7)
    const float* e   = (const float*)d_in[2];   // emission_probs (B, K, 4)
    const float* mus = (const float*)d_in[3];   // (B, E)
    const float* lv  = (const float*)d_in[4];   // (B, E)

    const int L = 128;
    int B = in_sizes[0] / L;
    int Edim = (B > 0) ? (in_sizes[3] / B) : 16;

    cudaMemsetAsync(d_out, 0, sizeof(float), 0);

    int warps = (B + 1) / 2;                   // one warp per 2 batch elements
    int threads = 256;                         // 8 warps/block
    int blocks = (warps * 32 + threads - 1) / threads;
    phmm_vae_kernel<<<blocks, threads>>>(x, a, e, mus, lv, (float*)d_out,
                                         B, Edim, 1.0f / (float)B);
}

// round 10
// speedup vs baseline: 1.3784x; 1.0105x over previous
#include <cuda_runtime.h>
#include <cstddef>

#define FULLMASK 0xffffffffu
typedef unsigned long long u64;

// ---- f32x2 packed helpers (sm_103a) ----
__device__ __forceinline__ u64 pk2(float lo, float hi) {
    u64 r; asm("mov.b64 %0, {%1, %2};" : "=l"(r) : "f"(lo), "f"(hi)); return r;
}
__device__ __forceinline__ void upk2(u64 v, float& lo, float& hi) {
    asm("mov.b64 {%0, %1}, %2;" : "=f"(lo), "=f"(hi) : "l"(v));
}
__device__ __forceinline__ u64 fma2(u64 a, u64 b, u64 c) {
    u64 d; asm("fma.rn.f32x2 %0, %1, %2, %3;" : "=l"(d) : "l"(a), "l"(b), "l"(c)); return d;
}
__device__ __forceinline__ u64 mul2(u64 a, u64 b) {
    u64 d; asm("mul.rn.f32x2 %0, %1, %2;" : "=l"(d) : "l"(a), "l"(b)); return d;
}

// Profile-HMM forward in scaled linear space.
// HALF-WARP per batch element; lane hl (0..15) owns states k = 4hl..4hl+3.
// Exclusive delete-prefix gx[hl] = g[4hl-1] computed as a scan over SHIFTED
// segment operators: gx[hl] = ts[hl] + Qs[hl]*gx[hl-1], where ts is assembled
// from two PARALLEL shuffles (t_loc up 1, p3prev up 2), then 4 KS levels.
// Rescaling uses a stale (1-iteration-delayed) power-of-two factor so the
// reduction runs off the critical chain.
__global__ void __launch_bounds__(256, 2)
phmm_vae_kernel(const int* __restrict__ x,
                const float* __restrict__ a,
                const float* __restrict__ e,
                const float* __restrict__ mus,
                const float* __restrict__ logvars,
                float* __restrict__ out,
                int B, int Edim, float inv_B)
{
    constexpr int K = 64;
    constexpr int L = 128;

    __shared__ float4 sem[8][2][4][16];   // [warp][half][sym][hl]

    int tid  = threadIdx.x;
    int wp   = tid >> 5;
    int lane = tid & 31;
    int hl   = lane & 15;
    int half = lane >> 4;
    int gwarp = blockIdx.x * 8 + wp;
    if (gwarp * 2 >= B) return;
    int bb  = gwarp * 2 + half;
    int bbc = min(bb, B - 1);

    const float* ab = a + (size_t)bbc * (K + 1) * 7;
    const float* eb = e + (size_t)bbc * K * 4;
    const int*   xb = x + (size_t)bbc * L;

    const int k0 = hl * 4;
    const float* A = ab + k0 * 7;

    // ---- per-state linear-space constants (enum: M2M,M2I,M2D,I2M,I2I,D2M,D2D) ----
    float c0 = __expf(A[6]),  c1s = __expf(A[13]),
          c2s = __expf(A[20]), c3 = __expf(A[27]);
    float M2D0 = __expf(A[2]),  M2D1 = __expf(A[9]),
          M2D2s = __expf(A[16]), M2D3 = __expf(A[23]);

    u64 M2MpA  = pk2(__expf(A[0]),  __expf(A[7]));
    u64 M2MpB  = pk2(__expf(A[14]), __expf(A[21]));
    u64 qM2IpA = pk2(0.25f*__expf(A[1]),  0.25f*__expf(A[8]));
    u64 qM2IpB = pk2(0.25f*__expf(A[15]), 0.25f*__expf(A[22]));
    u64 I2MpA  = pk2(__expf(A[3]),  __expf(A[10]));
    u64 I2MpB  = pk2(__expf(A[17]), __expf(A[24]));
    u64 qI2IpA = pk2(0.25f*__expf(A[4]),  0.25f*__expf(A[11]));
    u64 qI2IpB = pk2(0.25f*__expf(A[18]), 0.25f*__expf(A[25]));
    float D2M0 = __expf(A[5]),  D2M1 = __expf(A[12]),
          D2M2 = __expf(A[19]), D2M3 = __expf(A[26]);
    u64 D2MpA = pk2(D2M0, D2M1);
    u64 D2MpB = pk2(D2M2, D2M3);
    // D2M (x) fD-coef (1, c0, c0c1, c0c1c2)
    u64 cfDA = pk2(D2M0, D2M1 * c0);
    u64 cfDB = pk2(D2M2 * c0 * c1s, D2M3 * c0 * c1s * c2s);

    // scan segment weights: t = W0*fM0 + W1*fM1 + W2*fM2 + W3*fM3, out = g[4hl+3]
    float W3 = M2D3;
    float W2 = M2D2s * c3;
    float W1 = M2D1 * c2s * c3;
    float W0 = M2D0 * c1s * c2s * c3;
    float Q  = c0 * c1s * c2s * c3;
    u64 WLA = pk2(0.0f, W1);     // t_loc excludes the fM0 term
    u64 WLB = pk2(W2, W3);
    u64 M2DpA = pk2(M2D0, M2D1);

    // sink k = 64
    const float* A64 = ab + K * 7;
    float M2M64  = __expf(A64[0]);
    float qM2I64 = 0.25f * __expf(A64[1]);
    float I2M64  = __expf(A64[3]);
    float qI2I64 = 0.25f * __expf(A64[4]);
    float D2M64  = __expf(A64[5]);

    // ---- shifted segment constants ----
    float Qs  = __shfl_up_sync(FULLMASK, Q, 1);
    float W0s = __shfl_up_sync(FULLMASK, W0, 1);
    if (hl < 2) W0s = 0.0f;

    float Cq[4];
    {
        float Crun = Qs;
        #pragma unroll
        for (int s = 0; s < 4; s++) {
            Cq[s] = (hl >= (1 << s)) ? Crun : 0.0f;
            float Cin = __shfl_up_sync(FULLMASK, Crun, 1 << s);
            if (hl >= (1 << s)) Crun *= Cin;
        }
    }

    // ---- peel constants: gx at l=0 (init fM = basis e0) ----
    // gx_peel[hl] = M2D_0 * prod_{j=1..4hl-1} c_j  (hl>=1), else 0
    float gx_peel;
    {
        float Pr = (hl >= 1) ? Qs : 1.0f;      // inclusive product of Q over lanes < hl
        #pragma unroll
        for (int s = 0; s < 4; s++) {
            float Pin = __shfl_up_sync(FULLMASK, Pr, 1 << s);
            if (hl >= (1 << s)) Pr *= Pin;
        }
        float c00   = __shfl_sync(FULLMASK, c0,   lane & 16);
        float M2D00 = __shfl_sync(FULLMASK, M2D0, lane & 16);
        gx_peel = (hl >= 1) ? (M2D00 * Pr / c00) : 0.0f;
    }

    // ---- emissions -> linear -> smem ----
    {
        const float4* e4 = reinterpret_cast<const float4*>(eb) + k0;
        float4 r0 = e4[0], r1 = e4[1], r2 = e4[2], r3 = e4[3];
        sem[wp][half][0][hl] = make_float4(__expf(r0.x), __expf(r1.x), __expf(r2.x), __expf(r3.x));
        sem[wp][half][1][hl] = make_float4(__expf(r0.y), __expf(r1.y), __expf(r2.y), __expf(r3.y));
        sem[wp][half][2][hl] = make_float4(__expf(r0.z), __expf(r1.z), __expf(r2.z), __expf(r3.z));
        sem[wp][half][3][hl] = make_float4(__expf(r0.w), __expf(r1.w), __expf(r2.w), __expf(r3.w));
    }
    __syncwarp();
    const float4* semb = &sem[wp][half][0][hl];

    // ---- state init ----
    u64 fMA = (hl == 0) ? pk2(1.0f, 0.0f) : 0ull;
    u64 fMB = 0ull;
    u64 fIA = 0ull, fIB = 0ull;
    float fM64 = 0.0f, fI64 = 0.0f;
    float p3prev = 0.0f;
    int   S = 0;
    float sig = 1.0f;  u64 sig2 = pk2(1.0f, 1.0f);  int sePend = 0;
    const int bidx = (lane & 16) | 15;
    const unsigned hmask = half ? 0xFFFF0000u : 0x0000FFFFu;

#define SCAN_GX(GX_OUT) do {                                                 \
    u64 tl64_ = fma2(WLA, fMA, mul2(WLB, fMB));                              \
    float tlo_, thi_; upk2(tl64_, tlo_, thi_);                               \
    float t_loc_ = tlo_ + thi_;                                              \
    float Bv_ = __shfl_up_sync(FULLMASK, t_loc_, 1);                         \
    float Cv_ = __shfl_up_sync(FULLMASK, p3prev, 2);                         \
    float g_ = fmaf(W0s, Cv_, Bv_);                                          \
    g_ = (hl >= 1) ? g_ : 0.0f;                                              \
    g_ = fmaf(Cq[0], __shfl_up_sync(FULLMASK, g_, 1), g_);                   \
    g_ = fmaf(Cq[1], __shfl_up_sync(FULLMASK, g_, 2), g_);                   \
    g_ = fmaf(Cq[2], __shfl_up_sync(FULLMASK, g_, 4), g_);                   \
    g_ = fmaf(Cq[3], __shfl_up_sync(FULLMASK, g_, 8), g_);                   \
    GX_OUT = g_;                                                             \
} while (0)

#define STEP_REST(XV, GX, APPLY) do {                                        \
    float4 es_ = semb[(XV) * 16];                                            \
    u64 esA_ = pk2(es_.x, es_.y), esB_ = pk2(es_.z, es_.w);                  \
    u64 dA_ = mul2(M2DpA, fMA);                                              \
    float d0_, d1_; upk2(dA_, d0_, d1_);                                     \
    float fM2_, fM3_; upk2(fMB, fM2_, fM3_);                                 \
    float d2_ = M2D2s * fM2_;                                                \
    float b2_ = fmaf(c1s, d0_, d1_);                                         \
    float b3_ = fmaf(c2s, b2_, d2_);                                         \
    u64 bA_ = pk2(0.0f, d0_), bB_ = pk2(b2_, b3_);                           \
    u64 pbA_ = mul2(esA_, fma2(M2MpA, fMA, fma2(I2MpA, fIA, mul2(D2MpA, bA_)))); \
    u64 pbB_ = mul2(esB_, fma2(M2MpB, fMB, fma2(I2MpB, fIB, mul2(D2MpB, bB_)))); \
    u64 pcA_ = mul2(esA_, cfDA), pcB_ = mul2(esB_, cfDB);                    \
    u64 gx2_ = pk2((GX), (GX));                                              \
    u64 pA_ = fma2(pcA_, gx2_, pbA_);                                        \
    u64 pB_ = fma2(pcB_, gx2_, pbB_);                                        \
    if (APPLY) { pA_ = mul2(pA_, sig2); pB_ = mul2(pB_, sig2); }             \
    float p0_, p1_, p2_, p3_; upk2(pA_, p0_, p1_); upk2(pB_, p2_, p3_);      \
    float Av_ = __shfl_up_sync(FULLMASK, p3_, 1);                            \
    float plast_ = __shfl_sync(FULLMASK, p3_, bidx);                         \
    fIA = fma2(qM2IpA, fMA, mul2(qI2IpA, fIA));                              \
    fIB = fma2(qM2IpB, fMB, mul2(qI2IpB, fIB));                              \
    if (APPLY) { fIA = mul2(fIA, sig2); fIB = mul2(fIB, sig2); }             \
    fI64 = fmaf(qM2I64, fM64, qI2I64 * fI64);                                \
    if (APPLY) { fI64 *= sig; S += sePend; }                                 \
    fM64 = plast_;                                                           \
    fMA = pk2((hl == 0) ? 0.0f : Av_, p0_);                                  \
    fMB = pk2(p1_, p2_);                                                     \
    p3prev = p3_;                                                            \
    if (!(APPLY)) {                                                          \
        float m_ = fmaxf(fmaxf(fmaxf(p0_, p1_), fmaxf(p2_, p3_)),            \
                         fmaxf(fM64, fI64));                                 \
        float i0_, i1_, i2_, i3_;                                            \
        upk2(fIA, i0_, i1_); upk2(fIB, i2_, i3_);                            \
        m_ = fmaxf(m_, fmaxf(fmaxf(i0_, i1_), fmaxf(i2_, i3_)));             \
        unsigned mb_ = __reduce_max_sync(hmask, __float_as_uint(m_));        \
        int se_ = 127 - (int)(mb_ >> 23);                                    \
        se_ = max(-126, min(126, se_));                                      \
        sig = __int_as_float((unsigned)(127 + se_) << 23);                   \
        sig2 = pk2(sig, sig);                                                \
        sePend = se_;                                                        \
    }                                                                        \
} while (0)

    // ---- l = 0 (peel, closed-form gx; acts as a "compute" iteration) ----
    {
        int xv = xb[0];
        STEP_REST(xv, gx_peel, 0);
    }

    // ---- l = 1..124 : 31 groups of 4 (apply, compute, apply, compute) ----
    #pragma unroll 1
    for (int g = 0; g < 31; g++) {
        int lb = 4 * g + 1;
        int x0 = xb[lb], x1 = xb[lb+1], x2 = xb[lb+2], x3 = xb[lb+3];
        float gx;
        SCAN_GX(gx); STEP_REST(x0, gx, 1);
        SCAN_GX(gx); STEP_REST(x1, gx, 0);
        SCAN_GX(gx); STEP_REST(x2, gx, 1);
        SCAN_GX(gx); STEP_REST(x3, gx, 0);
    }

    // ---- l = 125, 126, 127 ----
    {
        int x0 = xb[125], x1 = xb[126], x2 = xb[127];
        float gx;
        SCAN_GX(gx); STEP_REST(x0, gx, 1);
        SCAN_GX(gx); STEP_REST(x1, gx, 0);
        SCAN_GX(gx); STEP_REST(x2, gx, 1);
    }

    // ---- final fD[64] = g[63] (lane 15) ----
    float fD64;
    {
        float gxf;
        SCAN_GX(gxf);
        u64 tl64 = fma2(WLA, fMA, mul2(WLB, fMB));
        float tlo, thi; upk2(tl64, tlo, thi);
        float fMA_lo, fMA_hi; upk2(fMA, fMA_lo, fMA_hi);
        float tfull = fmaf(W0, fMA_lo, tlo + thi);
        fD64 = fmaf(Q, gxf, tfull);
    }

    float fin  = fmaf(M2M64, fM64, fmaf(I2M64, fI64, D2M64 * fD64));
    float loss = (float)S * 0.69314718055994531f - logf(fin);

    // ---- KLD ----
    float kl = 0.0f;
    for (int i = hl; i < Edim; i += 16) {
        float mu = mus[(size_t)bbc * Edim + i];
        float lv = logvars[(size_t)bbc * Edim + i];
        kl += fmaf(mu, mu, __expf(lv)) - 1.0f - lv;
    }
    kl *= 0.5f;
    #pragma unroll
    for (int off = 8; off >= 1; off >>= 1)
        kl += __shfl_xor_sync(FULLMASK, kl, off);

    if (hl == 15 && bb < B)
        atomicAdd(out, (loss + kl) * inv_B);
#undef SCAN_GX
#undef STEP_REST
}

extern "C" void kernel_launch(void* const* d_in, const int* in_sizes, int n_in,
                              void* d_out, int out_size)
{
    const int*   x   = (const int*)  d_in[0];
    const float* a   = (const float*)d_in[1];
    const float* e   = (const float*)d_in[2];
    const float* mus = (const float*)d_in[3];
    const float* lv  = (const float*)d_in[4];

    const int L = 128;
    int B = in_sizes[0] / L;
    int Edim = (B > 0) ? (in_sizes[3] / B) : 16;

    cudaMemsetAsync(d_out, 0, sizeof(float), 0);

    int warps = (B + 1) / 2;
    int threads = 256;
    int blocks = (warps * 32 + threads - 1) / threads;
    phmm_vae_kernel<<<blocks, threads>>>(x, a, e, mus, lv, (float*)d_out,
                                         B, Edim, 1.0f / (float)B);
}

// round 14
// speedup vs baseline: 1.4525x; 1.0538x over previous
#include <cuda_runtime.h>
#include <cstddef>

#define FULLMASK 0xffffffffu
typedef unsigned long long u64;

// ---- f32x2 packed helpers (sm_103a) ----
__device__ __forceinline__ u64 pk2(float lo, float hi) {
    u64 r; asm("mov.b64 %0, {%1, %2};" : "=l"(r) : "f"(lo), "f"(hi)); return r;
}
__device__ __forceinline__ void upk2(u64 v, float& lo, float& hi) {
    asm("mov.b64 {%0, %1}, %2;" : "=f"(lo), "=f"(hi) : "l"(v));
}
__device__ __forceinline__ u64 fma2(u64 a, u64 b, u64 c) {
    u64 d; asm("fma.rn.f32x2 %0, %1, %2, %3;" : "=l"(d) : "l"(a), "l"(b), "l"(c)); return d;
}
__device__ __forceinline__ u64 mul2(u64 a, u64 b) {
    u64 d; asm("mul.rn.f32x2 %0, %1, %2;" : "=l"(d) : "l"(a), "l"(b)); return d;
}

// Profile-HMM forward in scaled linear space. ONE WARP per batch element.
// Lane j (0..31) owns states k = 2j, 2j+1 as one f32x2 pair.
// Exclusive delete-prefix gx[j] = g[2j-1] via scan over SHIFTED segment ops:
//   gx[j] = ts[j] + Qs[j]*gx[j-1],  ts assembled from two PARALLEL shuffles.
// k=64 sink tracked privately per lane (only lane 31's copy is real; no
// broadcast shuffle). Stale power-of-two rescale keeps the reduction off the
// critical chain.
__global__ void __launch_bounds__(256, 4)
phmm_vae_kernel(const int* __restrict__ x,
                const float* __restrict__ a,
                const float* __restrict__ e,
                const float* __restrict__ mus,
                const float* __restrict__ logvars,
                float* __restrict__ out,
                int B, int Edim, float inv_B)
{
    constexpr int K = 64;
    constexpr int L = 128;

    __shared__ u64 sem[8][4][32];   // [warp][sym][lane] packed emission pair, 8KB

    int tid  = threadIdx.x;
    int wp   = tid >> 5;
    int lane = tid & 31;
    int warp = blockIdx.x * 8 + wp;
    if (warp >= B) return;

    const float* ab = a + (size_t)warp * (K + 1) * 7;
    const float* eb = e + (size_t)warp * K * 4;
    const int*   xb = x + (size_t)warp * L;

    const float* A = ab + lane * 14;   // states 2*lane, 2*lane+1

    // ---- linear-space constants (enum: M2M,M2I,M2D,I2M,I2I,D2M,D2D) ----
    float c0   = __expf(A[6]);
    float c1   = __expf(A[13]);
    float M2D0 = __expf(A[2]);
    float M2D1 = __expf(A[9]);
    float D2M0 = __expf(A[5]);
    float D2M1 = __expf(A[12]);

    u64 M2Mp  = pk2(__expf(A[0]),        __expf(A[7]));
    u64 qM2Ip = pk2(0.25f*__expf(A[1]),  0.25f*__expf(A[8]));
    u64 I2Mp  = pk2(__expf(A[3]),        __expf(A[10]));
    u64 qI2Ip = pk2(0.25f*__expf(A[4]),  0.25f*__expf(A[11]));
    u64 cfD   = pk2(D2M0, D2M1 * c0);    // D2M x (1, c0) applied to gx

    // segment: g[2j+1] = t + Q*gx, t = W1*fM1 + W0*fM0
    float W1 = M2D1;
    float W0 = M2D0 * c1;
    float Q  = c0 * c1;

    // sink k = 64
    const float* A64 = ab + K * 7;
    float M2M64  = __expf(A64[0]);
    float qM2I64 = 0.25f * __expf(A64[1]);
    float I2M64  = __expf(A64[3]);
    float qI2I64 = 0.25f * __expf(A64[4]);
    float D2M64  = __expf(A64[5]);

    // ---- shifted segment constants ----
    float Qs  = __shfl_up_sync(FULLMASK, Q, 1);
    float W0s = __shfl_up_sync(FULLMASK, W0, 1);
    if (lane < 2) W0s = 0.0f;
    float W1s = __shfl_up_sync(FULLMASK, W1, 1);
    if (lane < 1) W1s = 0.0f;

    float Cq[5];
    {
        float Crun = Qs;
        #pragma unroll
        for (int s = 0; s < 5; s++) {
            Cq[s] = (lane >= (1 << s)) ? Crun : 0.0f;
            float Cin = __shfl_up_sync(FULLMASK, Crun, 1 << s);
            if (lane >= (1 << s)) Crun *= Cin;
        }
    }

    // ---- peel: gx at l=0 (init fM = basis e0) ----
    float gx_peel;
    {
        float Pr = (lane >= 1) ? Qs : 1.0f;
        #pragma unroll
        for (int s = 0; s < 5; s++) {
            float Pin = __shfl_up_sync(FULLMASK, Pr, 1 << s);
            if (lane >= (1 << s)) Pr *= Pin;
        }
        float c00   = __shfl_sync(FULLMASK, c0,   0);
        float M2D00 = __shfl_sync(FULLMASK, M2D0, 0);
        gx_peel = (lane >= 1) ? (M2D00 * Pr / c00) : 0.0f;
    }

    // ---- emissions -> linear -> smem (packed pair per symbol) ----
    {
        const float4* e4 = reinterpret_cast<const float4*>(eb) + lane * 2;
        float4 r0 = e4[0], r1 = e4[1];
        sem[wp][0][lane] = pk2(__expf(r0.x), __expf(r1.x));
        sem[wp][1][lane] = pk2(__expf(r0.y), __expf(r1.y));
        sem[wp][2][lane] = pk2(__expf(r0.z), __expf(r1.z));
        sem[wp][3][lane] = pk2(__expf(r0.w), __expf(r1.w));
    }
    __syncwarp();
    const u64* semb = &sem[wp][0][lane];   // + sym*32 per symbol

    // ---- state init ----
    float fM0s = (lane == 0) ? 1.0f : 0.0f;
    float fM1s = 0.0f;
    u64   fMp  = pk2(fM0s, fM1s);
    u64   fIp  = 0ull;
    float fM64 = 0.0f, fI64 = 0.0f;    // private sink copy (lane 31's is real)
    float p1prev = 0.0f;
    int   S = 0;
    float sig = 1.0f;  u64 sig2 = pk2(1.0f, 1.0f);  int sePend = 0;

#define SCAN_GX(GX_OUT) do {                                                 \
    float tl_ = W1s * __shfl_up_sync(FULLMASK, fM1s, 1);                     \
    float Cv_ = __shfl_up_sync(FULLMASK, p1prev, 2);                         \
    float g_ = fmaf(W0s, Cv_, tl_);                                          \
    g_ = fmaf(Cq[0], __shfl_up_sync(FULLMASK, g_, 1), g_);                   \
    g_ = fmaf(Cq[1], __shfl_up_sync(FULLMASK, g_, 2), g_);                   \
    g_ = fmaf(Cq[2], __shfl_up_sync(FULLMASK, g_, 4), g_);                   \
    g_ = fmaf(Cq[3], __shfl_up_sync(FULLMASK, g_, 8), g_);                   \
    g_ = fmaf(Cq[4], __shfl_up_sync(FULLMASK, g_, 16), g_);                  \
    GX_OUT = g_;                                                             \
} while (0)

#define STEP_REST(XV, GX, APPLY) do {                                        \
    u64 esp_ = semb[(XV) * 32];                                              \
    float d0_ = M2D0 * fM0s;                                                 \
    float bD_ = D2M1 * d0_;                                                  \
    u64 bP_ = pk2(0.0f, bD_);                                                \
    u64 pb_ = mul2(esp_, fma2(M2Mp, fMp, fma2(I2Mp, fIp, bP_)));             \
    u64 pc_ = mul2(esp_, cfD);                                               \
    u64 gx2_ = pk2((GX), (GX));                                              \
    u64 pP_ = fma2(pc_, gx2_, pb_);                                          \
    if (APPLY) { pP_ = mul2(pP_, sig2); }                                    \
    float p0_, p1_; upk2(pP_, p0_, p1_);                                     \
    float p1up_ = __shfl_up_sync(FULLMASK, p1_, 1);                          \
    fIp = fma2(qM2Ip, fMp, mul2(qI2Ip, fIp));                                \
    if (APPLY) { fIp = mul2(fIp, sig2); }                                    \
    fI64 = fmaf(qM2I64, fM64, qI2I64 * fI64);                                \
    if (APPLY) { fI64 *= sig; S += sePend; }                                 \
    fM64 = p1_;               /* private: only lane 31's is the real sink */ \
    fM0s = (lane == 0) ? 0.0f : p1up_;                                       \
    fM1s = p0_;                                                              \
    fMp = pk2(fM0s, fM1s);                                                   \
    p1prev = p1_;                                                            \
    if (!(APPLY)) {                                                          \
        float i0_, i1_; upk2(fIp, i0_, i1_);                                 \
        float m_ = fmaxf(fmaxf(fM0s, fM1s), fmaxf(i0_, i1_));                \
        m_ = fmaxf(m_, fmaxf(fM64, fI64));                                   \
        unsigned mb_ = __reduce_max_sync(FULLMASK, __float_as_uint(m_));     \
        int se_ = 127 - (int)(mb_ >> 23);                                    \
        se_ = max(-126, min(126, se_));                                      \
        sig = __int_as_float((unsigned)(127 + se_) << 23);                   \
        sig2 = pk2(sig, sig);                                                \
        sePend = se_;                                                        \
    }                                                                        \
} while (0)

    const int4* x4 = reinterpret_cast<const int4*>(xb);

    // ---- group 0: l = 0 (peeled gx), 1, 2, 3 ----
    {
        int4 xq = x4[0];
        float gx;
        STEP_REST(xq.x, gx_peel, 0);
        SCAN_GX(gx); STEP_REST(xq.y, gx, 1);
        SCAN_GX(gx); STEP_REST(xq.z, gx, 0);
        SCAN_GX(gx); STEP_REST(xq.w, gx, 1);
    }

    // ---- groups 1..31: l = 4g..4g+3, pattern (compute, apply, compute, apply) ----
    #pragma unroll 1
    for (int g = 1; g < L / 4; g++) {
        int4 xq = x4[g];
        float gx;
        SCAN_GX(gx); STEP_REST(xq.x, gx, 0);
        SCAN_GX(gx); STEP_REST(xq.y, gx, 1);
        SCAN_GX(gx); STEP_REST(xq.z, gx, 0);
        SCAN_GX(gx); STEP_REST(xq.w, gx, 1);
    }

    // ---- final fD[64] = g[63] (on lane 31, no broadcast needed) ----
    float fD64;
    {
        float gxf;
        SCAN_GX(gxf);
        float tfull = fmaf(W0, fM0s, W1 * fM1s);
        fD64 = fmaf(Q, gxf, tfull);
    }

    // lane 31 holds the true sink states
    float fin  = fmaf(M2M64, fM64, fmaf(I2M64, fI64, D2M64 * fD64));
    float loss = (float)S * 0.69314718055994531f - logf(fin);

    // ---- KLD ----
    float kl = 0.0f;
    for (int i = lane; i < Edim; i += 32) {
        float mu = mus[(size_t)warp * Edim + i];
        float lv = logvars[(size_t)warp * Edim + i];
        kl += fmaf(mu, mu, __expf(lv)) - 1.0f - lv;
    }
    kl *= 0.5f;
    #pragma unroll
    for (int off = 16; off >= 1; off >>= 1)
        kl += __shfl_xor_sync(FULLMASK, kl, off);

    if (lane == 31)
        atomicAdd(out, (loss + kl) * inv_B);
#undef SCAN_GX
#undef STEP_REST
}

extern "C" void kernel_launch(void* const* d_in, const int* in_sizes, int n_in,
                              void* d_out, int out_size)
{
    const int*   x   = (const int*)  d_in[0];
    const float* a   = (const float*)d_in[1];
    const float* e   = (const float*)d_in[2];
    const float* mus = (const float*)d_in[3];
    const float* lv  = (const float*)d_in[4];

    const int L = 128;
    int B = in_sizes[0] / L;
    int Edim = (B > 0) ? (in_sizes[3] / B) : 16;

    cudaMemsetAsync(d_out, 0, sizeof(float), 0);

    int threads = 256;                 // 8 warps/block, 1 warp per batch element
    int blocks = (B * 32 + threads - 1) / threads;
    phmm_vae_kernel<<<blocks, threads>>>(x, a, e, mus, lv, (float*)d_out,
                                         B, Edim, 1.0f / (float)B);
}

// round 15
// speedup vs baseline: 1.6162x; 1.1127x over previous
#include <cuda_runtime.h>
#include <cstddef>

#define FULLMASK 0xffffffffu
typedef unsigned long long u64;

// ---- f32x2 packed helpers (sm_103a) ----
__device__ __forceinline__ u64 pk2(float lo, float hi) {
    u64 r; asm("mov.b64 %0, {%1, %2};" : "=l"(r) : "f"(lo), "f"(hi)); return r;
}
__device__ __forceinline__ void upk2(u64 v, float& lo, float& hi) {
    asm("mov.b64 {%0, %1}, %2;" : "=f"(lo), "=f"(hi) : "l"(v));
}
__device__ __forceinline__ u64 fma2(u64 a, u64 b, u64 c) {
    u64 d; asm("fma.rn.f32x2 %0, %1, %2, %3;" : "=l"(d) : "l"(a), "l"(b), "l"(c)); return d;
}
__device__ __forceinline__ u64 mul2(u64 a, u64 b) {
    u64 d; asm("mul.rn.f32x2 %0, %1, %2;" : "=l"(d) : "l"(a), "l"(b)); return d;
}

// Profile-HMM forward, scaled linear space, WAVEFRONT schedule.
// One warp per batch element; lane j owns states k = 2j, 2j+1 and processes
// sequence step l = t - j at global iteration t. The delete-chain prefix
// arrives incrementally from lane j-1 (1 packed shuffle/iter) instead of a
// 5-level Kogge-Stone scan. Linear updates + zero init make fill/drain lanes
// self-consistently zero/garbage without predication; the final-state delete
// chain for fD[64] emerges at lane 31 at t = 159.
__global__ void __launch_bounds__(256, 4)
phmm_vae_kernel(const int* __restrict__ x,
                const float* __restrict__ a,
                const float* __restrict__ e,
                const float* __restrict__ mus,
                const float* __restrict__ logvars,
                float* __restrict__ out,
                int B, int Edim, float inv_B)
{
    constexpr int K = 64;
    constexpr int L = 128;

    __shared__ u64 sem[8][4][32];   // [warp][sym][lane] packed emission pair
    __shared__ int xs[8][192];      // padded symbols: xs[31+l] = x[l]

    int tid  = threadIdx.x;
    int wp   = tid >> 5;
    int lane = tid & 31;
    int warp = blockIdx.x * 8 + wp;
    if (warp >= B) return;

    const float* ab = a + (size_t)warp * (K + 1) * 7;
    const float* eb = e + (size_t)warp * K * 4;
    const int*   xb = x + (size_t)warp * L;

    const float* A = ab + lane * 14;   // states 2*lane, 2*lane+1

    // ---- linear-space constants (enum: M2M,M2I,M2D,I2M,I2I,D2M,D2D) ----
    float c0   = __expf(A[6]);
    float c1   = __expf(A[13]);
    float M2D0 = __expf(A[2]);
    float M2D1 = __expf(A[9]);
    float D2M0 = __expf(A[5]);
    float D2M1 = __expf(A[12]);

    u64 M2Mp  = pk2(__expf(A[0]),        __expf(A[7]));
    u64 qM2Ip = pk2(0.25f*__expf(A[1]),  0.25f*__expf(A[8]));
    u64 I2Mp  = pk2(__expf(A[3]),        __expf(A[10]));
    u64 qI2Ip = pk2(0.25f*__expf(A[4]),  0.25f*__expf(A[11]));
    u64 cfD   = pk2(D2M0, D2M1 * c0);    // D2M (x) (1, c0), applied to gx

    // segment: g[2j+1] = t_loc + Q*gx,  t_loc = W0*fM0 + W1*fM1
    float W1 = M2D1;
    float W0 = M2D0 * c1;
    float Q  = c0 * c1;

    // sink k = 64 (all lanes hold; only lane 31's copy is real)
    const float* A64 = ab + K * 7;
    float M2M64  = __expf(A64[0]);
    float qM2I64 = 0.25f * __expf(A64[1]);
    float I2M64  = __expf(A64[3]);
    float qI2I64 = 0.25f * __expf(A64[4]);
    float D2M64  = __expf(A64[5]);

    // ---- emissions -> linear -> smem (packed pair per symbol) ----
    {
        const float4* e4 = reinterpret_cast<const float4*>(eb) + lane * 2;
        float4 r0 = e4[0], r1 = e4[1];
        sem[wp][0][lane] = pk2(__expf(r0.x), __expf(r1.x));
        sem[wp][1][lane] = pk2(__expf(r0.y), __expf(r1.y));
        sem[wp][2][lane] = pk2(__expf(r0.z), __expf(r1.z));
        sem[wp][3][lane] = pk2(__expf(r0.w), __expf(r1.w));
    }
    // ---- padded symbol array ----
    for (int i = lane; i < 192; i += 32) {
        int l = i - 31;
        xs[wp][i] = (l >= 0 && l < L) ? xb[l] : 0;
    }
    __syncwarp();
    const u64* semb = &sem[wp][0][lane];     // + sym*32 per symbol
    const int* xsl  = &xs[wp][31 - lane];    // xsl[t] = symbol for step t-lane

    // ---- state ----
    float fM1s = 0.0f;                 // fM[2j+1] entering current step
    u64   fIp  = 0ull;                 // (fI[2j], fI[2j+1])
    float fM64 = 0.0f, fI64 = 0.0f;
    float g_last = 0.0f, p1_l1 = 0.0f, p1_l2 = 0.0f;   // in-flight history
    int   S = 0;

// one wavefront iteration (GX = delete prefix g[2j-1]; FM0 = fM[2j] entering)
#define CORE(GX, FM0, SYM, DO_RESC) do {                                     \
    u64 esp_ = semb[(SYM) * 32];                                             \
    float tl_   = fmaf(W0, (FM0), W1 * fM1s);                                \
    float gnew_ = fmaf(Q, (GX), tl_);                                        \
    float d0_ = M2D0 * (FM0);                                                \
    u64 bP_  = pk2(0.0f, D2M1 * d0_);                                        \
    u64 fMp_ = pk2((FM0), fM1s);                                             \
    u64 pb_  = mul2(esp_, fma2(M2Mp, fMp_, fma2(I2Mp, fIp, bP_)));           \
    u64 gx2_ = pk2((GX), (GX));                                              \
    u64 pP_  = fma2(mul2(esp_, cfD), gx2_, pb_);                             \
    float p0_, p1_; upk2(pP_, p0_, p1_);                                     \
    fIp  = fma2(qM2Ip, fMp_, mul2(qI2Ip, fIp));                              \
    fI64 = fmaf(qM2I64, fM64, qI2I64 * fI64);                                \
    fM64 = p1_;                                                              \
    fM1s = p0_;                                                              \
    p1_l2 = p1_l1; p1_l1 = p1_; g_last = gnew_;                              \
    if (DO_RESC) {                                                           \
        float i0_, i1_; upk2(fIp, i0_, i1_);                                 \
        float m_ = fmaxf(fmaxf(p0_, p1_), fmaxf(i0_, i1_));                  \
        m_ = fmaxf(m_, fmaxf(fM64, fI64));                                   \
        unsigned mb_ = __reduce_max_sync(FULLMASK, __float_as_uint(m_));     \
        int se_ = 119 - (int)(mb_ >> 23);     /* target max ~= 2^-8 */       \
        se_ = max(-126, min(126, se_));                                      \
        float sg_ = __int_as_float((unsigned)(127 + se_) << 23);             \
        S += se_;                                                            \
        u64 sg2_ = pk2(sg_, sg_);                                            \
        fM1s *= sg_;  fIp = mul2(fIp, sg2_);                                 \
        fM64 *= sg_;  fI64 *= sg_;                                           \
        g_last *= sg_; p1_l1 *= sg_; p1_l2 *= sg_;                           \
    }                                                                        \
} while (0)

#define RECV(GXV, FM0V)                                                      \
    u64 rcv_ = __shfl_up_sync(FULLMASK, pk2(g_last, p1_l2), 1);              \
    float GXV, FM0V; upk2(rcv_, GXV, FM0V);                                  \
    if (lane == 0) { GXV = 0.0f; FM0V = 0.0f; }

    // ---- t = 0 (no recv; only lane 0 has a nonzero input: fM[0] = 1) ----
    {
        int s0 = xsl[0];
        float f0 = (lane == 0) ? 1.0f : 0.0f;
        CORE(0.0f, f0, s0, 0);
    }
    // ---- t = 1..3 ----
    {
        int s1 = xsl[1], s2 = xsl[2], s3 = xsl[3];
        { RECV(gx, f0); CORE(gx, f0, s1, 0); }
        { RECV(gx, f0); CORE(gx, f0, s2, 0); }
        { RECV(gx, f0); CORE(gx, f0, s3, 1); }
    }
    // ---- t = 4..155 : 38 groups of 4 ----
    #pragma unroll 1
    for (int g = 1; g < 39; g++) {
        const int* xp = xsl + 4 * g;
        int s0 = xp[0], s1 = xp[1], s2 = xp[2], s3 = xp[3];
        { RECV(gx, f0); CORE(gx, f0, s0, 0); }
        { RECV(gx, f0); CORE(gx, f0, s1, 0); }
        { RECV(gx, f0); CORE(gx, f0, s2, 0); }
        { RECV(gx, f0); CORE(gx, f0, s3, 1); }
    }
    // ---- t = 156, 157, 158 (lane 31 finishes step 127 at t = 158) ----
    {
        int s0 = xsl[156], s1 = xsl[157], s2 = xsl[158];
        { RECV(gx, f0); CORE(gx, f0, s0, 0); }
        { RECV(gx, f0); CORE(gx, f0, s1, 0); }
        { RECV(gx, f0); CORE(gx, f0, s2, 0); }
    }
    // ---- epilogue t = 159: final delete chain -> fD[64] on lane 31 ----
    float fD64;
    {
        RECV(gx, f0);
        fD64 = fmaf(Q, gx, fmaf(W0, f0, W1 * fM1s));
    }

    // lane 31 holds the true sink states (entering step 128 = final)
    float fin  = fmaf(M2M64, fM64, fmaf(I2M64, fI64, D2M64 * fD64));
    float loss = (float)S * 0.69314718055994531f - logf(fin);

    // ---- KLD ----
    float kl = 0.0f;
    for (int i = lane; i < Edim; i += 32) {
        float mu = mus[(size_t)warp * Edim + i];
        float lv = logvars[(size_t)warp * Edim + i];
        kl += fmaf(mu, mu, __expf(lv)) - 1.0f - lv;
    }
    kl *= 0.5f;
    #pragma unroll
    for (int off = 16; off >= 1; off >>= 1)
        kl += __shfl_xor_sync(FULLMASK, kl, off);

    if (lane == 31)
        atomicAdd(out, (loss + kl) * inv_B);
#undef CORE
#undef RECV
}

extern "C" void kernel_launch(void* const* d_in, const int* in_sizes, int n_in,
                              void* d_out, int out_size)
{
    const int*   x   = (const int*)  d_in[0];
    const float* a   = (const float*)d_in[1];
    const float* e   = (const float*)d_in[2];
    const float* mus = (const float*)d_in[3];
    const float* lv  = (const float*)d_in[4];

    const int L = 128;
    int B = in_sizes[0] / L;
    int Edim = (B > 0) ? (in_sizes[3] / B) : 16;

    cudaMemsetAsync(d_out, 0, sizeof(float), 0);

    int threads = 256;                 // 8 warps/block, 1 warp per batch element
    int blocks = (B * 32 + threads - 1) / threads;
    phmm_vae_kernel<<<blocks, threads>>>(x, a, e, mus, lv, (float*)d_out,
                                         B, Edim, 1.0f / (float)B);
}

// round 16
// speedup vs baseline: 1.6646x; 1.0299x over previous
#include <cuda_runtime.h>
#include <cstddef>

#define FULLMASK 0xffffffffu
typedef unsigned long long u64;

// ---- f32x2 packed helpers (sm_103a) ----
__device__ __forceinline__ u64 pk2(float lo, float hi) {
    u64 r; asm("mov.b64 %0, {%1, %2};" : "=l"(r) : "f"(lo), "f"(hi)); return r;
}
__device__ __forceinline__ void upk2(u64 v, float& lo, float& hi) {
    asm("mov.b64 {%0, %1}, %2;" : "=f"(lo), "=f"(hi) : "l"(v));
}
__device__ __forceinline__ u64 fma2(u64 a, u64 b, u64 c) {
    u64 d; asm("fma.rn.f32x2 %0, %1, %2, %3;" : "=l"(d) : "l"(a), "l"(b), "l"(c)); return d;
}
__device__ __forceinline__ u64 mul2(u64 a, u64 b) {
    u64 d; asm("mul.rn.f32x2 %0, %1, %2;" : "=l"(d) : "l"(a), "l"(b)); return d;
}

// One independent pHMM chain (one batch element), wavefront-scheduled.
struct Chain {
    // constants (linear space)
    u64 M2Mp, qM2Ip, I2Mp, qI2Ip, cfD;
    float M2D0, D2M1, W0, W1, Q;
    float qM2I64, qI2I64;
    // state
    float fM1s; u64 fIp; float fM64, fI64;
    float g_last, p1_l1, p1_l2;
    int S;
    const u64* semb;
};

__device__ __forceinline__ void chain_init(Chain& C, const float* ab,
                                           const float* eb, u64* semw, int lane)
{
    const float* A = ab + lane * 14;   // states 2*lane, 2*lane+1
    float c0 = __expf(A[6]), c1 = __expf(A[13]);
    C.M2D0 = __expf(A[2]);
    float M2D1 = __expf(A[9]);
    float D2M0 = __expf(A[5]);
    C.D2M1 = __expf(A[12]);
    C.M2Mp  = pk2(__expf(A[0]),       __expf(A[7]));
    C.qM2Ip = pk2(0.25f*__expf(A[1]), 0.25f*__expf(A[8]));
    C.I2Mp  = pk2(__expf(A[3]),       __expf(A[10]));
    C.qI2Ip = pk2(0.25f*__expf(A[4]), 0.25f*__expf(A[11]));
    C.cfD   = pk2(D2M0, C.D2M1 * c0);
    C.W1 = M2D1;
    C.W0 = C.M2D0 * c1;
    C.Q  = c0 * c1;
    const float* A64 = ab + 64 * 7;
    C.qM2I64 = 0.25f * __expf(A64[1]);
    C.qI2I64 = 0.25f * __expf(A64[4]);
    // emissions -> linear -> smem (packed pair per symbol)
    const float4* e4 = reinterpret_cast<const float4*>(eb) + lane * 2;
    float4 r0 = e4[0], r1 = e4[1];
    semw[0 * 32 + lane] = pk2(__expf(r0.x), __expf(r1.x));
    semw[1 * 32 + lane] = pk2(__expf(r0.y), __expf(r1.y));
    semw[2 * 32 + lane] = pk2(__expf(r0.z), __expf(r1.z));
    semw[3 * 32 + lane] = pk2(__expf(r0.w), __expf(r1.w));
    C.semb = &semw[lane];
    C.fM1s = 0.0f; C.fIp = 0ull; C.fM64 = 0.0f; C.fI64 = 0.0f;
    C.g_last = 0.0f; C.p1_l1 = 0.0f; C.p1_l2 = 0.0f; C.S = 0;
}

__device__ __forceinline__ void chain_recv(Chain& C, int lane, float& gx, float& f0)
{
    u64 rcv = __shfl_up_sync(FULLMASK, pk2(C.g_last, C.p1_l2), 1);
    upk2(rcv, gx, f0);
    if (lane == 0) { gx = 0.0f; f0 = 0.0f; }
}

__device__ __forceinline__ void chain_core(Chain& C, float gx, float f0, int sym)
{
    u64 esp = C.semb[sym * 32];
    float tl   = fmaf(C.W0, f0, C.W1 * C.fM1s);
    float gnew = fmaf(C.Q, gx, tl);
    float d0 = C.M2D0 * f0;
    u64 bP  = pk2(0.0f, C.D2M1 * d0);
    u64 fMp = pk2(f0, C.fM1s);
    u64 pb  = mul2(esp, fma2(C.M2Mp, fMp, fma2(C.I2Mp, C.fIp, bP)));
    u64 pP  = fma2(mul2(esp, C.cfD), pk2(gx, gx), pb);
    float p0, p1; upk2(pP, p0, p1);
    C.fIp  = fma2(C.qM2Ip, fMp, mul2(C.qI2Ip, C.fIp));
    C.fI64 = fmaf(C.qM2I64, C.fM64, C.qI2I64 * C.fI64);
    C.fM64 = p1;
    C.fM1s = p0;
    C.p1_l2 = C.p1_l1; C.p1_l1 = p1; C.g_last = gnew;
}

__device__ __forceinline__ void chain_resc(Chain& C)
{
    float i0, i1; upk2(C.fIp, i0, i1);
    float m = fmaxf(fmaxf(C.fM1s, C.fM64), fmaxf(i0, i1));
    m = fmaxf(m, C.fI64);
    unsigned mb = __reduce_max_sync(FULLMASK, __float_as_uint(m));
    int se = 119 - (int)(mb >> 23);          // target max ~= 2^-8
    se = max(-126, min(126, se));
    float sg = __int_as_float((unsigned)(127 + se) << 23);
    C.S += se;
    u64 sg2 = pk2(sg, sg);
    C.fM1s *= sg; C.fIp = mul2(C.fIp, sg2);
    C.fM64 *= sg; C.fI64 *= sg;
    C.g_last *= sg; C.p1_l1 *= sg; C.p1_l2 *= sg;
}

// Wavefront pHMM, TWO batch elements per warp (per-thread ILP-2).
// Lane j owns states 2j, 2j+1 of both chains; sequence step l = t - j.
__global__ void __launch_bounds__(64, 8)
phmm_vae_kernel(const int* __restrict__ x,
                const float* __restrict__ a,
                const float* __restrict__ e,
                const float* __restrict__ mus,
                const float* __restrict__ logvars,
                float* __restrict__ out,
                int B, int Edim, float inv_B)
{
    constexpr int K = 64;
    constexpr int L = 128;

    __shared__ u64 sem[2][2][4][32];   // [warp][chain][sym][lane]
    __shared__ int xsp[2][192];        // packed symbols: symA | symB<<16

    int tid  = threadIdx.x;
    int wp   = tid >> 5;
    int lane = tid & 31;
    int gwarp = blockIdx.x * 2 + wp;
    if (gwarp * 2 >= B) return;
    int bA = gwarp * 2;
    int bB = gwarp * 2 + 1;
    bool hasB = (bB < B);
    int bBc = hasB ? bB : bA;

    const float* abA = a + (size_t)bA * (K + 1) * 7;
    const float* abB = a + (size_t)bBc * (K + 1) * 7;
    const int* xA = x + (size_t)bA * L;
    const int* xB = x + (size_t)bBc * L;

    Chain CA, CB;
    chain_init(CA, abA, e + (size_t)bA  * K * 4, &sem[wp][0][0][0], lane);
    chain_init(CB, abB, e + (size_t)bBc * K * 4, &sem[wp][1][0][0], lane);

    // padded packed symbols: xsp[31 + l] = xA[l] | xB[l]<<16
    for (int i = lane; i < 192; i += 32) {
        int l = i - 31;
        int sA = (l >= 0 && l < L) ? xA[l] : 0;
        int sB = (l >= 0 && l < L) ? xB[l] : 0;
        xsp[wp][i] = sA | (sB << 16);
    }
    __syncwarp();
    const int* xsl = &xsp[wp][31 - lane];   // xsl[t] = packed syms for step t-lane

    // ---- t = 0 ----
    {
        int v = xsl[0];
        float f0 = (lane == 0) ? 1.0f : 0.0f;
        chain_core(CA, 0.0f, f0, v & 0xffff);
        chain_core(CB, 0.0f, f0, v >> 16);
    }
    // ---- t = 1..3 ----
    #pragma unroll
    for (int t = 1; t < 4; t++) {
        int v = xsl[t];
        float gA, fA, gB, fB;
        chain_recv(CA, lane, gA, fA);
        chain_recv(CB, lane, gB, fB);
        chain_core(CA, gA, fA, v & 0xffff);
        chain_core(CB, gB, fB, v >> 16);
    }
    chain_resc(CA); chain_resc(CB);

    // ---- t = 4..155 : 38 groups of 4 ----
    #pragma unroll 1
    for (int g = 1; g < 39; g++) {
        const int* xp = xsl + 4 * g;
        #pragma unroll
        for (int s = 0; s < 4; s++) {
            int v = xp[s];
            float gA, fA, gB, fB;
            chain_recv(CA, lane, gA, fA);
            chain_recv(CB, lane, gB, fB);
            chain_core(CA, gA, fA, v & 0xffff);
            chain_core(CB, gB, fB, v >> 16);
        }
        chain_resc(CA); chain_resc(CB);
    }

    // ---- t = 156..158 (lane 31 finishes step 127 at t = 158) ----
    #pragma unroll
    for (int t = 156; t < 159; t++) {
        int v = xsl[t];
        float gA, fA, gB, fB;
        chain_recv(CA, lane, gA, fA);
        chain_recv(CB, lane, gB, fB);
        chain_core(CA, gA, fA, v & 0xffff);
        chain_core(CB, gB, fB, v >> 16);
    }

    // ---- epilogue t = 159: final delete chain -> fD[64] on lane 31 ----
    float fD64A, fD64B;
    {
        float gA, fA, gB, fB;
        chain_recv(CA, lane, gA, fA);
        chain_recv(CB, lane, gB, fB);
        fD64A = fmaf(CA.Q, gA, fmaf(CA.W0, fA, CA.W1 * CA.fM1s));
        fD64B = fmaf(CB.Q, gB, fmaf(CB.W0, fB, CB.W1 * CB.fM1s));
    }

    // lane 31 holds the true sink states; reload final-transition constants
    const float* A64a = abA + K * 7;
    const float* A64b = abB + K * 7;
    float finA = fmaf(__expf(A64a[0]), CA.fM64,
                 fmaf(__expf(A64a[3]), CA.fI64, __expf(A64a[5]) * fD64A));
    float finB = fmaf(__expf(A64b[0]), CB.fM64,
                 fmaf(__expf(A64b[3]), CB.fI64, __expf(A64b[5]) * fD64B));
    const float LN2 = 0.69314718055994531f;
    float lossA = (float)CA.S * LN2 - logf(finA);
    float lossB = (float)CB.S * LN2 - logf(finB);

    // ---- KLD for both batch elements ----
    float klA = 0.0f, klB = 0.0f;
    for (int i = lane; i < Edim; i += 32) {
        float muA = mus[(size_t)bA * Edim + i];
        float lvA = logvars[(size_t)bA * Edim + i];
        klA += fmaf(muA, muA, __expf(lvA)) - 1.0f - lvA;
        float muB = mus[(size_t)bBc * Edim + i];
        float lvB = logvars[(size_t)bBc * Edim + i];
        klB += fmaf(muB, muB, __expf(lvB)) - 1.0f - lvB;
    }
    #pragma unroll
    for (int off = 16; off >= 1; off >>= 1) {
        klA += __shfl_xor_sync(FULLMASK, klA, off);
        klB += __shfl_xor_sync(FULLMASK, klB, off);
    }

    if (lane == 31) {
        float contrib = lossA + 0.5f * klA;
        if (hasB) contrib += lossB + 0.5f * klB;
        atomicAdd(out, contrib * inv_B);
    }
}

extern "C" void kernel_launch(void* const* d_in, const int* in_sizes, int n_in,
                              void* d_out, int out_size)
{
    const int*   x   = (const int*)  d_in[0];
    const float* a   = (const float*)d_in[1];
    const float* e   = (const float*)d_in[2];
    const float* mus = (const float*)d_in[3];
    const float* lv  = (const float*)d_in[4];

    const int L = 128;
    int B = in_sizes[0] / L;
    int Edim = (B > 0) ? (in_sizes[3] / B) : 16;

    cudaMemsetAsync(d_out, 0, sizeof(float), 0);

    int warps = (B + 1) / 2;           // one warp per 2 batch elements
    int threads = 64;                  // 2 warps/block -> ~1024 blocks, good balance
    int blocks = (warps * 32 + threads - 1) / threads;
    phmm_vae_kernel<<<blocks, threads>>>(x, a, e, mus, lv, (float*)d_out,
                                         B, Edim, 1.0f / (float)B);
}

// round 17
// speedup vs baseline: 1.7965x; 1.0793x over previous
#include <cuda_runtime.h>
#include <cstddef>

#define FULLMASK 0xffffffffu
typedef unsigned long long u64;

// ---- f32x2 packed helpers (sm_103a) ----
__device__ __forceinline__ u64 pk2(float lo, float hi) {
    u64 r; asm("mov.b64 %0, {%1, %2};" : "=l"(r) : "f"(lo), "f"(hi)); return r;
}
__device__ __forceinline__ void upk2(u64 v, float& lo, float& hi) {
    asm("mov.b64 {%0, %1}, %2;" : "=f"(lo), "=f"(hi) : "l"(v));
}
__device__ __forceinline__ u64 fma2(u64 a, u64 b, u64 c) {
    u64 d; asm("fma.rn.f32x2 %0, %1, %2, %3;" : "=l"(d) : "l"(a), "l"(b), "l"(c)); return d;
}
__device__ __forceinline__ u64 mul2(u64 a, u64 b) {
    u64 d; asm("mul.rn.f32x2 %0, %1, %2;" : "=l"(d) : "l"(a), "l"(b)); return d;
}

// Profile-HMM forward, scaled linear space, WAVEFRONT schedule, HALF-WARP per
// batch element. Lane hl (0..15) of each half owns states k = 4hl..4hl+3 and
// processes sequence step l = t - hl at iteration t. One instruction stream
// serves BOTH chains (SIMT halves). Delete-chain prefix gx = fD[4hl] arrives
// incrementally from lane hl-1 (packed shuffle: g 1-iter delay, boundary fM
// 2-iter delay). Fill/drain lanes are self-consistently zero/garbage.
__global__ void __launch_bounds__(64, 8)
phmm_vae_kernel(const int* __restrict__ x,
                const float* __restrict__ a,
                const float* __restrict__ e,
                const float* __restrict__ mus,
                const float* __restrict__ logvars,
                float* __restrict__ out,
                int B, int Edim, float inv_B)
{
    constexpr int K = 64;
    constexpr int L = 128;

    __shared__ float4 sem[2][2][4][16];   // [warp][half][sym][hl]
    __shared__ int    xs[2][2][160];      // [warp][half][15+l] padded symbols

    int tid  = threadIdx.x;
    int wp   = tid >> 5;
    int lane = tid & 31;
    int hl   = lane & 15;
    int half = lane >> 4;
    int gwarp = blockIdx.x * 2 + wp;
    if (gwarp * 2 >= B) return;
    int bb  = gwarp * 2 + half;
    int bbc = min(bb, B - 1);

    const float* ab = a + (size_t)bbc * (K + 1) * 7;
    const float* eb = e + (size_t)bbc * K * 4;
    const int*   xb = x + (size_t)bbc * L;

    const float* A = ab + hl * 28;   // transition rows 4hl..4hl+3

    // ---- linear-space constants (enum: M2M,M2I,M2D,I2M,I2I,D2M,D2D) ----
    float c1 = __expf(A[13]), c2 = __expf(A[20]), c3 = __expf(A[27]);
    float c0 = __expf(A[6]);
    u64 M2DpA = pk2(__expf(A[2]),  __expf(A[9]));
    u64 M2DpB = pk2(__expf(A[16]), __expf(A[23]));
    float D2M0 = __expf(A[5]),  D2M1 = __expf(A[12]);
    float D2M2 = __expf(A[19]), D2M3 = __expf(A[26]);
    u64 D2MpB = pk2(D2M2, D2M3);

    u64 M2MpA  = pk2(__expf(A[0]),        __expf(A[7]));
    u64 M2MpB  = pk2(__expf(A[14]),       __expf(A[21]));
    u64 qM2IpA = pk2(0.25f*__expf(A[1]),  0.25f*__expf(A[8]));
    u64 qM2IpB = pk2(0.25f*__expf(A[15]), 0.25f*__expf(A[22]));
    u64 I2MpA  = pk2(__expf(A[3]),        __expf(A[10]));
    u64 I2MpB  = pk2(__expf(A[17]),       __expf(A[24]));
    u64 qI2IpA = pk2(0.25f*__expf(A[4]),  0.25f*__expf(A[11]));
    u64 qI2IpB = pk2(0.25f*__expf(A[18]), 0.25f*__expf(A[25]));

    float cc01 = c0 * c1;
    u64 cfDA = pk2(D2M0, D2M1 * c0);            // D2M_i * cf_i, i = 0,1
    u64 cfDB = pk2(D2M2 * cc01, D2M3 * cc01 * c2);
    float Q3 = cc01 * c2 * c3;                  // full segment multiplier

    const float* A64 = ab + K * 7;
    float qM2I64 = 0.25f * __expf(A64[1]);
    float qI2I64 = 0.25f * __expf(A64[4]);

    // ---- emissions -> linear -> smem ----
    {
        const float4* e4 = reinterpret_cast<const float4*>(eb) + hl * 4;
        float4 r0 = e4[0], r1 = e4[1], r2 = e4[2], r3 = e4[3];
        sem[wp][half][0][hl] = make_float4(__expf(r0.x), __expf(r1.x), __expf(r2.x), __expf(r3.x));
        sem[wp][half][1][hl] = make_float4(__expf(r0.y), __expf(r1.y), __expf(r2.y), __expf(r3.y));
        sem[wp][half][2][hl] = make_float4(__expf(r0.z), __expf(r1.z), __expf(r2.z), __expf(r3.z));
        sem[wp][half][3][hl] = make_float4(__expf(r0.w), __expf(r1.w), __expf(r2.w), __expf(r3.w));
    }
    // ---- padded symbols: xs[15 + l] = x[l] ----
    for (int i = hl; i < 160; i += 16) {
        int l = i - 15;
        xs[wp][half][i] = (l >= 0 && l < L) ? xb[l] : 0;
    }
    __syncwarp();
    const float4* semb = &sem[wp][half][0][hl];   // + sym*16 per symbol
    const int*    xsl  = &xs[wp][half][15 - hl];  // xsl[t] = symbol for step t-hl

    // ---- state ----
    float fM1 = 0.0f, fM2 = 0.0f, fM3 = 0.0f;   // fM[4hl+1..3] entering step
    u64   fIA = 0ull, fIB = 0ull;               // fI[4hl..4hl+3]
    float fM64 = 0.0f, fI64 = 0.0f;             // sink (hl==15 real)
    float g_last = 0.0f, p3_l1 = 0.0f, p3_l2 = 0.0f;
    int   S = 0;
    const unsigned hmask = half ? 0xFFFF0000u : 0x0000FFFFu;

#define BODY(SYM, GX, F0) do {                                               \
    float4 es_ = semb[(SYM) * 16];                                           \
    u64 esA_ = pk2(es_.x, es_.y), esB_ = pk2(es_.z, es_.w);                  \
    u64 fMpA_ = pk2((F0), fM1), fMpB_ = pk2(fM2, fM3);                       \
    u64 dA_ = mul2(M2DpA, fMpA_);                                            \
    u64 dB_ = mul2(M2DpB, fMpB_);                                            \
    float d0_, d1_, d2_, d3_; upk2(dA_, d0_, d1_); upk2(dB_, d2_, d3_);      \
    float b2_ = fmaf(c1, d0_, d1_);                                          \
    float b3_ = fmaf(c2, b2_, d2_);                                          \
    float tb_ = fmaf(c3, b3_, d3_);                                          \
    u64 bPA_ = pk2(0.0f, D2M1 * d0_);                                        \
    u64 bPB_ = mul2(D2MpB, pk2(b2_, b3_));                                   \
    u64 pbA_ = mul2(esA_, fma2(M2MpA, fMpA_, fma2(I2MpA, fIA, bPA_)));       \
    u64 pbB_ = mul2(esB_, fma2(M2MpB, fMpB_, fma2(I2MpB, fIB, bPB_)));       \
    u64 gx2_ = pk2((GX), (GX));                                              \
    u64 pA_ = fma2(mul2(esA_, cfDA), gx2_, pbA_);                            \
    u64 pB_ = fma2(mul2(esB_, cfDB), gx2_, pbB_);                            \
    float p0_, p1_, p2_, p3_; upk2(pA_, p0_, p1_); upk2(pB_, p2_, p3_);      \
    fIA = fma2(qM2IpA, fMpA_, mul2(qI2IpA, fIA));                            \
    fIB = fma2(qM2IpB, fMpB_, mul2(qI2IpB, fIB));                            \
    fI64 = fmaf(qM2I64, fM64, qI2I64 * fI64);                                \
    fM64 = p3_;                                                              \
    fM1 = p0_; fM2 = p1_; fM3 = p2_;                                         \
    p3_l2 = p3_l1; p3_l1 = p3_;                                              \
    g_last = fmaf(Q3, (GX), tb_);                                            \
} while (0)

#define CORE(T) do {                                                         \
    int sym_ = xsl[T];                                                       \
    u64 rcv_ = __shfl_up_sync(FULLMASK, pk2(g_last, p3_l2), 1);              \
    float gx_, f0_; upk2(rcv_, gx_, f0_);                                    \
    if (hl == 0) { gx_ = 0.0f; f0_ = 0.0f; }                                 \
    BODY(sym_, gx_, f0_);                                                    \
} while (0)

#define RESC() do {                                                          \
    float i0_, i1_, i2_, i3_;                                                \
    upk2(fIA, i0_, i1_); upk2(fIB, i2_, i3_);                                \
    float m_ = fmaxf(fmaxf(fM1, fM2), fmaxf(fM3, fM64));                     \
    m_ = fmaxf(m_, fmaxf(fmaxf(i0_, i1_), fmaxf(i2_, i3_)));                 \
    m_ = fmaxf(m_, fI64);                                                    \
    unsigned mb_ = __reduce_max_sync(hmask, __float_as_uint(m_));            \
    int se_ = 119 - (int)(mb_ >> 23);       /* target max ~= 2^-8 */         \
    se_ = max(-126, min(126, se_));                                          \
    float sg_ = __int_as_float((unsigned)(127 + se_) << 23);                 \
    S += se_;                                                                \
    u64 sg2_ = pk2(sg_, sg_);                                                \
    fM1 *= sg_; fM2 *= sg_; fM3 *= sg_;                                      \
    fIA = mul2(fIA, sg2_); fIB = mul2(fIB, sg2_);                            \
    fM64 *= sg_; fI64 *= sg_;                                                \
    g_last *= sg_; p3_l1 *= sg_; p3_l2 *= sg_;                               \
} while (0)

    // ---- t = 0 (no recv; lane 0 of each half injects fM[0] = 1) ----
    {
        int sym = xsl[0];
        float f0 = (hl == 0) ? 1.0f : 0.0f;
        BODY(sym, 0.0f, f0);
    }
    CORE(1); CORE(2); CORE(3); RESC();

    // ---- t = 4..139 : 34 groups of 4 ----
    #pragma unroll 1
    for (int g = 1; g < 35; g++) {
        const int t0 = 4 * g;   // compiler keeps xsl+t0 as one add; offsets imm
        CORE(t0); CORE(t0 + 1); CORE(t0 + 2); CORE(t0 + 3);
        RESC();
    }

    // ---- t = 140..142 (lane 15 finishes step 127 at t = 142) ----
    CORE(140); CORE(141); CORE(142);

    // ---- epilogue t = 143: final delete chain -> fD[64] on lane 15 ----
    float fD64;
    {
        u64 rcv = __shfl_up_sync(FULLMASK, pk2(g_last, p3_l2), 1);
        float gx, f0; upk2(rcv, gx, f0);
        if (hl == 0) { gx = 0.0f; f0 = 0.0f; }
        u64 fMpA = pk2(f0, fM1), fMpB = pk2(fM2, fM3);
        u64 dA = mul2(M2DpA, fMpA);
        u64 dB = mul2(M2DpB, fMpB);
        float d0, d1, d2, d3; upk2(dA, d0, d1); upk2(dB, d2, d3);
        float b2 = fmaf(c1, d0, d1);
        float b3 = fmaf(c2, b2, d2);
        float tb = fmaf(c3, b3, d3);
        fD64 = fmaf(Q3, gx, tb);
    }

    // ---- final logsumexp (lane hl==15 holds true sink states) ----
    float fin  = fmaf(__expf(A64[0]), fM64,
                 fmaf(__expf(A64[3]), fI64, __expf(A64[5]) * fD64));
    float loss = (float)S * 0.69314718055994531f - logf(fin);

    // ---- KLD (16 lanes per batch element) ----
    float kl = 0.0f;
    for (int i = hl; i < Edim; i += 16) {
        float mu = mus[(size_t)bbc * Edim + i];
        float lv = logvars[(size_t)bbc * Edim + i];
        kl += fmaf(mu, mu, __expf(lv)) - 1.0f - lv;
    }
    kl *= 0.5f;
    #pragma unroll
    for (int off = 8; off >= 1; off >>= 1)
        kl += __shfl_xor_sync(FULLMASK, kl, off);   // stays within half

    if (hl == 15 && bb < B)
        atomicAdd(out, (loss + kl) * inv_B);
#undef BODY
#undef CORE
#undef RESC
}

extern "C" void kernel_launch(void* const* d_in, const int* in_sizes, int n_in,
                              void* d_out, int out_size)
{
    const int*   x   = (const int*)  d_in[0];
    const float* a   = (const float*)d_in[1];
    const float* e   = (const float*)d_in[2];
    const float* mus = (const float*)d_in[3];
    const float* lv  = (const float*)d_in[4];

    const int L = 128;
    int B = in_sizes[0] / L;
    int Edim = (B > 0) ? (in_sizes[3] / B) : 16;

    cudaMemsetAsync(d_out, 0, sizeof(float), 0);

    int warps = (B + 1) / 2;           // one warp per 2 batch elements
    int threads = 64;                  // 2 warps/block -> ~1024 blocks
    int blocks = (warps * 32 + threads - 1) / threads;
    phmm_vae_kernel<<<blocks, threads>>>(x, a, e, mus, lv, (float*)d_out,
                                         B, Edim, 1.0f / (float)B);
}